// round 3
// baseline (speedup 1.0000x reference)
#include <cuda_runtime.h>

typedef unsigned long long ull;

#define TPB 128
#define NSAMP 3
#define N_HIDDEN 30
#define H 16
#define S_IN 13

// ---- packed f32x2 helpers (sm_103a; FFMA2 only reachable via PTX) ----
__device__ __forceinline__ ull pack2(float lo, float hi){
    ull r; asm("mov.b64 %0, {%1, %2};" : "=l"(r) : "f"(lo), "f"(hi)); return r;
}
__device__ __forceinline__ ull dup2(float v){
    ull r; asm("mov.b64 %0, {%1, %1};" : "=l"(r) : "f"(v)); return r;
}
__device__ __forceinline__ void unpack2(ull v, float& lo, float& hi){
    asm("mov.b64 {%0, %1}, %2;" : "=f"(lo), "=f"(hi) : "l"(v));
}
__device__ __forceinline__ ull fma2(ull a, ull b, ull c){
    ull d; asm("fma.rn.f32x2 %0, %1, %2, %3;" : "=l"(d) : "l"(a), "l"(b), "l"(c)); return d;
}

__global__ __launch_bounds__(TPB, 4)
void mlp_kernel(const float* __restrict__ x,
                const float* __restrict__ W_in,  const float* __restrict__ b_in,
                const float* __restrict__ W_h,   const float* __restrict__ b_h,
                const float* __restrict__ W_out, const float* __restrict__ b_out,
                float* __restrict__ out, int T, int B)
{
    // Weights repacked as j-pair f32x2: s_wh[l][k][jp] = (W[2jp][k], W[2jp+1][k])
    __shared__ __align__(16) ull   s_win[S_IN * 8];
    __shared__ __align__(16) ull   s_bin[8];
    __shared__ __align__(16) ull   s_wh[N_HIDDEN * H * 8];
    __shared__ __align__(16) ull   s_bh[N_HIDDEN * 8];
    __shared__ __align__(16) ull   s_wout[8];
    __shared__ float s_bout;

    const int t = threadIdx.x;

    for (int i = t; i < S_IN * 8; i += TPB){
        int k = i >> 3, jp = i & 7;
        s_win[i] = pack2(W_in[(2*jp)*S_IN + k], W_in[(2*jp+1)*S_IN + k]);
    }
    if (t < 8){
        s_bin[t]  = pack2(b_in[2*t],  b_in[2*t+1]);
        s_wout[t] = pack2(W_out[2*t], W_out[2*t+1]);
    }
    for (int i = t; i < N_HIDDEN * H * 8; i += TPB){
        int l = i >> 7; int r = i & 127; int k = r >> 3, jp = r & 7;
        const float* Wl = W_h + l * (H * H);
        s_wh[i] = pack2(Wl[(2*jp)*H + k], Wl[(2*jp+1)*H + k]);
    }
    for (int i = t; i < N_HIDDEN * 8; i += TPB){
        int l = i >> 3, jp = i & 7;
        s_bh[i] = pack2(b_h[l*H + 2*jp], b_h[l*H + 2*jp + 1]);
    }
    if (t == 0) s_bout = b_out[0];
    __syncthreads();

    const int g = blockIdx.x * TPB + t;
    if (g >= T) return;

    // samples g, g+T, g+2T (clamped loads, guarded stores for the tail)
    int   sidx[NSAMP];
    bool  valid[NSAMP];
#pragma unroll
    for (int s = 0; s < NSAMP; s++){
        int idx = g + s * T;
        valid[s] = (idx < B);
        sidx[s]  = valid[s] ? idx : (B - 1);
    }

    float h[NSAMP][H];

    // ---------- input layer: [13] -> [16], bias folded into k==0 FMA ----------
    {
        ull a[NSAMP][8];
#pragma unroll
        for (int k = 0; k < S_IN; k++){
            ull hk[NSAMP];
#pragma unroll
            for (int s = 0; s < NSAMP; s++)
                hk[s] = dup2(x[(size_t)sidx[s] * S_IN + k]);
#pragma unroll
            for (int jp = 0; jp < 8; jp++){
                ull w = s_win[k*8 + jp];
#pragma unroll
                for (int s = 0; s < NSAMP; s++)
                    a[s][jp] = fma2(w, hk[s], (k == 0) ? s_bin[jp] : a[s][jp]);
            }
        }
#pragma unroll
        for (int s = 0; s < NSAMP; s++)
#pragma unroll
            for (int jp = 0; jp < 8; jp++){
                float lo, hi; unpack2(a[s][jp], lo, hi);
                h[s][2*jp]   = fmaxf(lo, 0.f);
                h[s][2*jp+1] = fmaxf(hi, 0.f);
            }
    }

    // ---------- 30 hidden layers (rolled loop, weight loads pipelined 1 k ahead) ----------
    const ull* wl = s_wh;
    const ull* bl = s_bh;
    for (int l = 0; l < N_HIDDEN; l++){
        ull a[NSAMP][8];

        const ulonglong2* wv = reinterpret_cast<const ulonglong2*>(wl);
        ulonglong2 c0 = wv[0], c1 = wv[1], c2 = wv[2], c3 = wv[3];   // k=0 weights

#pragma unroll
        for (int k = 0; k < H; k++){
            ull w[8] = {c0.x, c0.y, c1.x, c1.y, c2.x, c2.y, c3.x, c3.y};
            if (k + 1 < H){                       // prefetch k+1
                const ulonglong2* wn = reinterpret_cast<const ulonglong2*>(wl + (k+1)*8);
                c0 = wn[0]; c1 = wn[1]; c2 = wn[2]; c3 = wn[3];
            }
            ull hk[NSAMP];
#pragma unroll
            for (int s = 0; s < NSAMP; s++) hk[s] = dup2(h[s][k]);
#pragma unroll
            for (int jp = 0; jp < 8; jp++){
#pragma unroll
                for (int s = 0; s < NSAMP; s++)
                    a[s][jp] = fma2(w[jp], hk[s], (k == 0) ? bl[jp] : a[s][jp]);
            }
        }
#pragma unroll
        for (int s = 0; s < NSAMP; s++)
#pragma unroll
            for (int jp = 0; jp < 8; jp++){
                float lo, hi; unpack2(a[s][jp], lo, hi);
                h[s][2*jp]   = fmaxf(lo, 0.f);
                h[s][2*jp+1] = fmaxf(hi, 0.f);
            }
        wl += H * 8;
        bl += 8;
    }

    // ---------- output layer: dot16 + b_out ----------
#pragma unroll
    for (int s = 0; s < NSAMP; s++){
        ull acc = pack2(s_bout, 0.f);
#pragma unroll
        for (int i = 0; i < 8; i++)
            acc = fma2(s_wout[i], pack2(h[s][2*i], h[s][2*i+1]), acc);
        float lo, hi; unpack2(acc, lo, hi);
        if (valid[s]) out[sidx[s]] = lo + hi;
    }
}

extern "C" void kernel_launch(void* const* d_in, const int* in_sizes, int n_in,
                              void* d_out, int out_size)
{
    const float* x     = (const float*)d_in[0];
    const float* W_in  = (const float*)d_in[1];
    const float* b_in  = (const float*)d_in[2];
    const float* W_h   = (const float*)d_in[3];
    const float* b_h   = (const float*)d_in[4];
    const float* W_out = (const float*)d_in[5];
    const float* b_out = (const float*)d_in[6];
    float* out = (float*)d_out;

    int B = out_size;                     // 2^21
    int T = (B + NSAMP - 1) / NSAMP;      // threads; samples g, g+T, g+2T
    int blocks = (T + TPB - 1) / TPB;
    mlp_kernel<<<blocks, TPB>>>(x, W_in, b_in, W_h, b_h, W_out, b_out, out, T, B);
}

// round 4
// speedup vs baseline: 1.0145x; 1.0145x over previous
#include <cuda_runtime.h>

typedef unsigned long long ull;

#define TPB 128
#define NSAMP 4
#define N_HIDDEN 30
#define H 16
#define S_IN 13

// ---- packed f32x2 helpers (sm_103a; FFMA2 only reachable via PTX) ----
__device__ __forceinline__ ull pack2(float lo, float hi){
    ull r; asm("mov.b64 %0, {%1, %2};" : "=l"(r) : "f"(lo), "f"(hi)); return r;
}
__device__ __forceinline__ ull dup2(float v){
    ull r; asm("mov.b64 %0, {%1, %1};" : "=l"(r) : "f"(v)); return r;
}
__device__ __forceinline__ void unpack2(ull v, float& lo, float& hi){
    asm("mov.b64 {%0, %1}, %2;" : "=f"(lo), "=f"(hi) : "l"(v));
}
__device__ __forceinline__ ull fma2(ull a, ull b, ull c){
    ull d; asm("fma.rn.f32x2 %0, %1, %2, %3;" : "=l"(d) : "l"(a), "l"(b), "l"(c)); return d;
}

// One hidden layer: h (per-sample scalars) -> h, using j-pair packed weights.
__device__ __forceinline__ void hidden_layer(float h[NSAMP][H], const ull* __restrict__ wl,
                                             const ull* __restrict__ bl)
{
    ull a[NSAMP][8];
#pragma unroll
    for (int k = 0; k < H; k++){
        ull hk[NSAMP];
#pragma unroll
        for (int s = 0; s < NSAMP; s++) hk[s] = dup2(h[s][k]);

        const ulonglong2* wk = reinterpret_cast<const ulonglong2*>(wl + k*8);
        ulonglong2 w01 = wk[0], w23 = wk[1], w45 = wk[2], w67 = wk[3];
        ull w[8] = {w01.x, w01.y, w23.x, w23.y, w45.x, w45.y, w67.x, w67.y};
#pragma unroll
        for (int jp = 0; jp < 8; jp++){
#pragma unroll
            for (int s = 0; s < NSAMP; s++)
                a[s][jp] = fma2(w[jp], hk[s], (k == 0) ? bl[jp] : a[s][jp]);
        }
    }
#pragma unroll
    for (int s = 0; s < NSAMP; s++)
#pragma unroll
        for (int jp = 0; jp < 8; jp++){
            float lo, hi; unpack2(a[s][jp], lo, hi);
            h[s][2*jp]   = fmaxf(lo, 0.f);
            h[s][2*jp+1] = fmaxf(hi, 0.f);
        }
}

__global__ __launch_bounds__(TPB, 3)
void mlp_kernel(const float* __restrict__ x,
                const float* __restrict__ W_in,  const float* __restrict__ b_in,
                const float* __restrict__ W_h,   const float* __restrict__ b_h,
                const float* __restrict__ W_out, const float* __restrict__ b_out,
                float* __restrict__ out, int quarter)
{
    // Weights repacked as j-pair f32x2: s_wh[l][k][jp] = (W[2jp][k], W[2jp+1][k])
    __shared__ __align__(16) ull   s_win[S_IN * 8];
    __shared__ __align__(16) ull   s_bin[8];
    __shared__ __align__(16) ull   s_wh[N_HIDDEN * H * 8];
    __shared__ __align__(16) ull   s_bh[N_HIDDEN * 8];
    __shared__ __align__(16) ull   s_wout[8];
    __shared__ float s_bout;

    const int t = threadIdx.x;

    for (int i = t; i < S_IN * 8; i += TPB){
        int k = i >> 3, jp = i & 7;
        s_win[i] = pack2(W_in[(2*jp)*S_IN + k], W_in[(2*jp+1)*S_IN + k]);
    }
    if (t < 8){
        s_bin[t]  = pack2(b_in[2*t],  b_in[2*t+1]);
        s_wout[t] = pack2(W_out[2*t], W_out[2*t+1]);
    }
    for (int i = t; i < N_HIDDEN * H * 8; i += TPB){
        int l = i >> 7; int r = i & 127; int k = r >> 3, jp = r & 7;
        const float* Wl = W_h + l * (H * H);
        s_wh[i] = pack2(Wl[(2*jp)*H + k], Wl[(2*jp+1)*H + k]);
    }
    for (int i = t; i < N_HIDDEN * 8; i += TPB){
        int l = i >> 3, jp = i & 7;
        s_bh[i] = pack2(b_h[l*H + 2*jp], b_h[l*H + 2*jp + 1]);
    }
    if (t == 0) s_bout = b_out[0];
    __syncthreads();

    const int g = blockIdx.x * TPB + t;
    if (g >= quarter) return;
    const int Q = quarter;   // samples: g, g+Q, g+2Q, g+3Q (coalesced stores)

    float h[NSAMP][H];

    // ---------- input layer: [13] -> [16], bias folded into k==0 FMA ----------
    {
        ull a[NSAMP][8];
#pragma unroll
        for (int k = 0; k < S_IN; k++){
            ull hk[NSAMP];
#pragma unroll
            for (int s = 0; s < NSAMP; s++)
                hk[s] = dup2(x[(size_t)(g + s*Q) * S_IN + k]);
#pragma unroll
            for (int jp = 0; jp < 8; jp++){
                ull w = s_win[k*8 + jp];
#pragma unroll
                for (int s = 0; s < NSAMP; s++)
                    a[s][jp] = fma2(w, hk[s], (k == 0) ? s_bin[jp] : a[s][jp]);
            }
        }
#pragma unroll
        for (int s = 0; s < NSAMP; s++)
#pragma unroll
            for (int jp = 0; jp < 8; jp++){
                float lo, hi; unpack2(a[s][jp], lo, hi);
                h[s][2*jp]   = fmaxf(lo, 0.f);
                h[s][2*jp+1] = fmaxf(hi, 0.f);
            }
    }

    // ---------- 30 hidden layers, unrolled x2: cross-layer scheduling window ----------
    const ull* wl = s_wh;
    const ull* bl = s_bh;
#pragma unroll 1
    for (int l = 0; l < N_HIDDEN / 2; l++){
        hidden_layer(h, wl,          bl);
        hidden_layer(h, wl + H*8,    bl + 8);
        wl += 2 * H * 8;
        bl += 2 * 8;
    }

    // ---------- output layer: dot16 + b_out ----------
#pragma unroll
    for (int s = 0; s < NSAMP; s++){
        ull acc = pack2(s_bout, 0.f);
#pragma unroll
        for (int i = 0; i < 8; i++)
            acc = fma2(s_wout[i], pack2(h[s][2*i], h[s][2*i+1]), acc);
        float lo, hi; unpack2(acc, lo, hi);
        out[g + s*Q] = lo + hi;
    }
}

extern "C" void kernel_launch(void* const* d_in, const int* in_sizes, int n_in,
                              void* d_out, int out_size)
{
    const float* x     = (const float*)d_in[0];
    const float* W_in  = (const float*)d_in[1];
    const float* b_in  = (const float*)d_in[2];
    const float* W_h   = (const float*)d_in[3];
    const float* b_h   = (const float*)d_in[4];
    const float* W_out = (const float*)d_in[5];
    const float* b_out = (const float*)d_in[6];
    float* out = (float*)d_out;

    int n = out_size;             // B = 2^21 (divisible by 4)
    int quarter = n >> 2;
    int blocks = (quarter + TPB - 1) / TPB;
    mlp_kernel<<<blocks, TPB>>>(x, W_in, b_in, W_h, b_h, W_out, b_out, out, quarter);
}

// round 7
// speedup vs baseline: 1.7212x; 1.6965x over previous
#include <cuda_runtime.h>
#include <cuda_bf16.h>
#include <cstdint>

#define TPB      256
#define MREP     4              // m16 tiles per warp
#define SPW      (MREP * 16)    // 64 samples per warp
#define SPC      (SPW * 8)      // 512 samples per CTA
#define NLAYERS  31             // input layer + 30 hidden
#define H        16
#define S_IN     13

// pack two f32 into bf16x2 (low half = a, high half = b)
__device__ __forceinline__ uint32_t cvt_bf16x2(float a, float b){
    uint32_t r;
    asm("cvt.rn.satfinite.bf16x2.f32 %0, %1, %2;" : "=r"(r) : "f"(b), "f"(a));
    return r;
}
// split (a,b) -> hi bf16x2 + lo bf16x2 (two-term decomposition)
__device__ __forceinline__ void split_pair(float a, float b, uint32_t& hi, uint32_t& lo){
    hi = cvt_bf16x2(a, b);
    float fa = __uint_as_float(hi << 16);
    float fb = __uint_as_float(hi & 0xFFFF0000u);
    lo = cvt_bf16x2(a - fa, b - fb);
}

// D += A(16x16 bf16, row) * B(16x8 bf16, col);  D/A/C fragments per PTX ISA
__device__ __forceinline__ void mma16816(float d[4], const uint32_t a[4],
                                         uint32_t b0, uint32_t b1){
    asm volatile(
        "mma.sync.aligned.m16n8k16.row.col.f32.bf16.bf16.f32 "
        "{%0,%1,%2,%3}, {%4,%5,%6,%7}, {%8,%9}, {%0,%1,%2,%3};"
        : "+f"(d[0]), "+f"(d[1]), "+f"(d[2]), "+f"(d[3])
        : "r"(a[0]), "r"(a[1]), "r"(a[2]), "r"(a[3]), "r"(b0), "r"(b1));
}

__global__ __launch_bounds__(TPB, 2)
void mlp_hmma_kernel(const float* __restrict__ x,
                     const float* __restrict__ W_in,  const float* __restrict__ b_in,
                     const float* __restrict__ W_h,   const float* __restrict__ b_h,
                     const float* __restrict__ W_out, const float* __restrict__ b_out,
                     float* __restrict__ out, int B)
{
    // B-fragments per lane: {whi_r0, whi_r1, wlo_r0, wlo_r1} -> one LDS.128/tile/layer
    __shared__ uint4  s_wf[NLAYERS][2][32];
    __shared__ float4 s_b4[NLAYERS][4];
    __shared__ float  s_wout[16];
    __shared__ float  s_bout;

    const int t = threadIdx.x;

    // ---- weight prep: fragment order, bf16 hi/lo ----
    for (int e = t; e < NLAYERS * 2 * 32; e += TPB){
        int l = e >> 6, r = e & 63, tile = r >> 5, tt = r & 31;
        int n = (tt >> 2) + tile * 8, i = tt & 3;
        float w[4];
#pragma unroll
        for (int j = 0; j < 4; j++){
            int k = 2*i + (j & 1) + (j >> 1) * 8;
            if (l == 0) w[j] = (k < S_IN) ? W_in[n * S_IN + k] : 0.f;
            else        w[j] = W_h[(l - 1) * (H * H) + n * H + k];
        }
        uint32_t h0, l0, h1, l1;
        split_pair(w[0], w[1], h0, l0);
        split_pair(w[2], w[3], h1, l1);
        s_wf[l][tile][tt] = make_uint4(h0, h1, l0, l1);
    }
    for (int e = t; e < NLAYERS * 4; e += TPB){
        int l = e >> 2, i = e & 3;
        const float* bb = (l == 0) ? b_in : (b_h + (l - 1) * H);
        s_b4[l][i] = make_float4(bb[2*i], bb[2*i+1], bb[2*i+8], bb[2*i+9]);
    }
    if (t < 16) s_wout[t] = W_out[t];
    if (t == 0) s_bout = b_out[0];
    __syncthreads();

    const int wid  = t >> 5;
    const int lane = t & 31;
    const int g    = lane >> 2;     // row group (0..7)
    const int i4   = lane & 3;      // col group (0..3)
    const int base = blockIdx.x * SPC + wid * SPW;

    // ---- A fragments for round 0: x rows {g, g+8}, cols {2i,2i+1,2i+8,2i+9} ----
    uint32_t Ahi[MREP][4], Alo[MREP][4];
#pragma unroll
    for (int m = 0; m < MREP; m++){
        const float* x0 = x + (size_t)(base + m*16 + g)     * S_IN;
        const float* x1 = x + (size_t)(base + m*16 + g + 8) * S_IN;
        float v0[4], v1[4];
#pragma unroll
        for (int j = 0; j < 4; j++){
            int k = 2*i4 + (j & 1) + (j >> 1) * 8;
            v0[j] = (k < S_IN) ? x0[k] : 0.f;
            v1[j] = (k < S_IN) ? x1[k] : 0.f;
        }
        split_pair(v0[0], v0[1], Ahi[m][0], Alo[m][0]);   // row g,   cols 2i,2i+1
        split_pair(v1[0], v1[1], Ahi[m][1], Alo[m][1]);   // row g+8, cols 2i,2i+1
        split_pair(v0[2], v0[3], Ahi[m][2], Alo[m][2]);   // row g,   cols +8
        split_pair(v1[2], v1[3], Ahi[m][3], Alo[m][3]);   // row g+8, cols +8
    }

    // ---- 30 chained layers (produce next A), rolled loop ----
#pragma unroll 1
    for (int l = 0; l < NLAYERS - 1; l++){
        uint4  wf0 = s_wf[l][0][lane];
        uint4  wf1 = s_wf[l][1][lane];
        float4 b4  = s_b4[l][i4];
#pragma unroll
        for (int m = 0; m < MREP; m++){
            float d0[4] = {0.f,0.f,0.f,0.f}, d1[4] = {0.f,0.f,0.f,0.f};
            mma16816(d0, Ahi[m], wf0.x, wf0.y);
            mma16816(d0, Ahi[m], wf0.z, wf0.w);
            mma16816(d0, Alo[m], wf0.x, wf0.y);
            mma16816(d1, Ahi[m], wf1.x, wf1.y);
            mma16816(d1, Ahi[m], wf1.z, wf1.w);
            mma16816(d1, Alo[m], wf1.x, wf1.y);

            float h00 = fmaxf(d0[0] + b4.x, 0.f);   // row g,   col 2i
            float h01 = fmaxf(d0[1] + b4.y, 0.f);   // row g,   col 2i+1
            float h02 = fmaxf(d0[2] + b4.x, 0.f);   // row g+8, col 2i
            float h03 = fmaxf(d0[3] + b4.y, 0.f);   // row g+8, col 2i+1
            float h10 = fmaxf(d1[0] + b4.z, 0.f);   // row g,   col 2i+8
            float h11 = fmaxf(d1[1] + b4.w, 0.f);
            float h12 = fmaxf(d1[2] + b4.z, 0.f);
            float h13 = fmaxf(d1[3] + b4.w, 0.f);

            split_pair(h00, h01, Ahi[m][0], Alo[m][0]);
            split_pair(h02, h03, Ahi[m][1], Alo[m][1]);
            split_pair(h10, h11, Ahi[m][2], Alo[m][2]);
            split_pair(h12, h13, Ahi[m][3], Alo[m][3]);
        }
    }

    // ---- final hidden layer + output dot, fused ----
    {
        const int l = NLAYERS - 1;
        uint4  wf0 = s_wf[l][0][lane];
        uint4  wf1 = s_wf[l][1][lane];
        float4 b4  = s_b4[l][i4];
        float wo0 = s_wout[2*i4],     wo1 = s_wout[2*i4 + 1];
        float wo2 = s_wout[2*i4 + 8], wo3 = s_wout[2*i4 + 9];
#pragma unroll
        for (int m = 0; m < MREP; m++){
            float d0[4] = {0.f,0.f,0.f,0.f}, d1[4] = {0.f,0.f,0.f,0.f};
            mma16816(d0, Ahi[m], wf0.x, wf0.y);
            mma16816(d0, Ahi[m], wf0.z, wf0.w);
            mma16816(d0, Alo[m], wf0.x, wf0.y);
            mma16816(d1, Ahi[m], wf1.x, wf1.y);
            mma16816(d1, Ahi[m], wf1.z, wf1.w);
            mma16816(d1, Alo[m], wf1.x, wf1.y);

            // rows g / g+8: partial dot over this lane's 4 columns
            float p0 = fmaxf(d0[0] + b4.x, 0.f) * wo0
                     + fmaxf(d0[1] + b4.y, 0.f) * wo1
                     + fmaxf(d1[0] + b4.z, 0.f) * wo2
                     + fmaxf(d1[1] + b4.w, 0.f) * wo3;
            float p1 = fmaxf(d0[2] + b4.x, 0.f) * wo0
                     + fmaxf(d0[3] + b4.y, 0.f) * wo1
                     + fmaxf(d1[2] + b4.z, 0.f) * wo2
                     + fmaxf(d1[3] + b4.w, 0.f) * wo3;
            p0 += __shfl_xor_sync(0xFFFFFFFFu, p0, 1);
            p0 += __shfl_xor_sync(0xFFFFFFFFu, p0, 2);
            p1 += __shfl_xor_sync(0xFFFFFFFFu, p1, 1);
            p1 += __shfl_xor_sync(0xFFFFFFFFu, p1, 2);
            if (i4 == 0){
                int s0 = base + m*16 + g;
                if (s0     < B) out[s0]     = p0 + s_bout;
                if (s0 + 8 < B) out[s0 + 8] = p1 + s_bout;
            }
        }
    }
}

extern "C" void kernel_launch(void* const* d_in, const int* in_sizes, int n_in,
                              void* d_out, int out_size)
{
    const float* x     = (const float*)d_in[0];
    const float* W_in  = (const float*)d_in[1];
    const float* b_in  = (const float*)d_in[2];
    const float* W_h   = (const float*)d_in[3];
    const float* b_h   = (const float*)d_in[4];
    const float* W_out = (const float*)d_in[5];
    const float* b_out = (const float*)d_in[6];
    float* out = (float*)d_out;

    int B = out_size;                    // 2^21, divisible by 512
    int grid = (B + SPC - 1) / SPC;      // 4096
    mlp_hmma_kernel<<<grid, TPB>>>(x, W_in, b_in, W_h, b_h, W_out, b_out, out, B);
}

// round 9
// speedup vs baseline: 1.7322x; 1.0064x over previous
#include <cuda_runtime.h>
#include <cuda_bf16.h>
#include <cstdint>

#define TPB      128
#define MREP     4              // m16 tiles per warp
#define SPW      (MREP * 16)    // 64 samples per warp
#define NWARP    (TPB / 32)
#define SPC      (SPW * NWARP)  // 256 samples per CTA
#define NLAYERS  31             // input layer + 30 hidden
#define H        16
#define S_IN     13

// pack two f32 into bf16x2 (low half = a, high half = b)
__device__ __forceinline__ uint32_t cvt_bf16x2(float a, float b){
    uint32_t r;
    asm("cvt.rn.satfinite.bf16x2.f32 %0, %1, %2;" : "=r"(r) : "f"(b), "f"(a));
    return r;
}
// split (a,b) -> hi bf16x2 + lo bf16x2 (two-term decomposition)
__device__ __forceinline__ void split_pair(float a, float b, uint32_t& hi, uint32_t& lo){
    hi = cvt_bf16x2(a, b);
    float fa = __uint_as_float(hi << 16);
    float fb = __uint_as_float(hi & 0xFFFF0000u);
    lo = cvt_bf16x2(a - fa, b - fb);
}

// D += A(16x16 bf16, row) * B(16x8 bf16, col)
__device__ __forceinline__ void mma16816(float d[4], const uint32_t a[4],
                                         uint32_t b0, uint32_t b1){
    asm volatile(
        "mma.sync.aligned.m16n8k16.row.col.f32.bf16.bf16.f32 "
        "{%0,%1,%2,%3}, {%4,%5,%6,%7}, {%8,%9}, {%0,%1,%2,%3};"
        : "+f"(d[0]), "+f"(d[1]), "+f"(d[2]), "+f"(d[3])
        : "r"(a[0]), "r"(a[1]), "r"(a[2]), "r"(a[3]), "r"(b0), "r"(b1));
}
// D = A*B + C  (C = bias fragment; starts a fresh accumulator chain)
__device__ __forceinline__ void mma16816_c(float d[4], const uint32_t a[4],
                                           uint32_t b0, uint32_t b1,
                                           float c0, float c1){
    asm volatile(
        "mma.sync.aligned.m16n8k16.row.col.f32.bf16.bf16.f32 "
        "{%0,%1,%2,%3}, {%4,%5,%6,%7}, {%8,%9}, {%10,%11,%10,%11};"
        : "=f"(d[0]), "=f"(d[1]), "=f"(d[2]), "=f"(d[3])
        : "r"(a[0]), "r"(a[1]), "r"(a[2]), "r"(a[3]), "r"(b0), "r"(b1),
          "f"(c0), "f"(c1));
}

__global__ __launch_bounds__(TPB, 5)
void mlp_hmma_kernel(const float* __restrict__ x,
                     const float* __restrict__ W_in,  const float* __restrict__ b_in,
                     const float* __restrict__ W_h,   const float* __restrict__ b_h,
                     const float* __restrict__ W_out, const float* __restrict__ b_out,
                     float* __restrict__ out, int B)
{
    // B-fragments per lane: {whi_r0, whi_r1, wlo_r0, wlo_r1} -> one LDS.128/tile/layer
    __shared__ uint4  s_wf[NLAYERS][2][32];
    __shared__ float4 s_b4[NLAYERS][4];
    __shared__ float  s_wout[16];
    __shared__ float  s_bout;

    const int t = threadIdx.x;

    // ---- weight prep: fragment order, bf16 hi/lo ----
    for (int e = t; e < NLAYERS * 2 * 32; e += TPB){
        int l = e >> 6, r = e & 63, tile = r >> 5, tt = r & 31;
        int n = (tt >> 2) + tile * 8, i = tt & 3;
        float w[4];
#pragma unroll
        for (int j = 0; j < 4; j++){
            int k = 2*i + (j & 1) + (j >> 1) * 8;
            if (l == 0) w[j] = (k < S_IN) ? W_in[n * S_IN + k] : 0.f;
            else        w[j] = W_h[(l - 1) * (H * H) + n * H + k];
        }
        uint32_t h0, l0, h1, l1;
        split_pair(w[0], w[1], h0, l0);
        split_pair(w[2], w[3], h1, l1);
        s_wf[l][tile][tt] = make_uint4(h0, h1, l0, l1);
    }
    for (int e = t; e < NLAYERS * 4; e += TPB){
        int l = e >> 2, i = e & 3;
        const float* bb = (l == 0) ? b_in : (b_h + (l - 1) * H);
        s_b4[l][i] = make_float4(bb[2*i], bb[2*i+1], bb[2*i+8], bb[2*i+9]);
    }
    if (t < 16) s_wout[t] = W_out[t];
    if (t == 0) s_bout = b_out[0];
    __syncthreads();

    const int wid  = t >> 5;
    const int lane = t & 31;
    const int g    = lane >> 2;     // row group (0..7)
    const int i4   = lane & 3;      // col group (0..3)
    const int base = blockIdx.x * SPC + wid * SPW;

    // ---- A fragments for round 0: x rows {g, g+8}, cols {2i,2i+1,2i+8,2i+9} ----
    uint32_t Ahi[MREP][4], Alo[MREP][4];
#pragma unroll
    for (int m = 0; m < MREP; m++){
        const float* x0 = x + (size_t)(base + m*16 + g)     * S_IN;
        const float* x1 = x + (size_t)(base + m*16 + g + 8) * S_IN;
        float v0[4], v1[4];
#pragma unroll
        for (int j = 0; j < 4; j++){
            int k = 2*i4 + (j & 1) + (j >> 1) * 8;
            v0[j] = (k < S_IN) ? x0[k] : 0.f;
            v1[j] = (k < S_IN) ? x1[k] : 0.f;
        }
        split_pair(v0[0], v0[1], Ahi[m][0], Alo[m][0]);
        split_pair(v1[0], v1[1], Ahi[m][1], Alo[m][1]);
        split_pair(v0[2], v0[3], Ahi[m][2], Alo[m][2]);
        split_pair(v1[2], v1[3], Ahi[m][3], Alo[m][3]);
    }

    // ---- 30 chained layers: da = Ahi*Whi + bias  ||  db = Ahi*Wlo + Alo*Whi ----
#pragma unroll 1
    for (int l = 0; l < NLAYERS - 1; l++){
        uint4  wf0 = s_wf[l][0][lane];
        uint4  wf1 = s_wf[l][1][lane];
        float4 b4  = s_b4[l][i4];
#pragma unroll
        for (int m = 0; m < MREP; m++){
            float da0[4], da1[4];
            float db0[4] = {0.f,0.f,0.f,0.f}, db1[4] = {0.f,0.f,0.f,0.f};
            mma16816_c(da0, Ahi[m], wf0.x, wf0.y, b4.x, b4.y);
            mma16816  (db0, Ahi[m], wf0.z, wf0.w);
            mma16816  (db0, Alo[m], wf0.x, wf0.y);
            mma16816_c(da1, Ahi[m], wf1.x, wf1.y, b4.z, b4.w);
            mma16816  (db1, Ahi[m], wf1.z, wf1.w);
            mma16816  (db1, Alo[m], wf1.x, wf1.y);

            float h00 = fmaxf(da0[0] + db0[0], 0.f);
            float h01 = fmaxf(da0[1] + db0[1], 0.f);
            float h02 = fmaxf(da0[2] + db0[2], 0.f);
            float h03 = fmaxf(da0[3] + db0[3], 0.f);
            float h10 = fmaxf(da1[0] + db1[0], 0.f);
            float h11 = fmaxf(da1[1] + db1[1], 0.f);
            float h12 = fmaxf(da1[2] + db1[2], 0.f);
            float h13 = fmaxf(da1[3] + db1[3], 0.f);

            split_pair(h00, h01, Ahi[m][0], Alo[m][0]);
            split_pair(h02, h03, Ahi[m][1], Alo[m][1]);
            split_pair(h10, h11, Ahi[m][2], Alo[m][2]);
            split_pair(h12, h13, Ahi[m][3], Alo[m][3]);
        }
    }

    // ---- final hidden layer + output dot, fused ----
    {
        const int l = NLAYERS - 1;
        uint4  wf0 = s_wf[l][0][lane];
        uint4  wf1 = s_wf[l][1][lane];
        float4 b4  = s_b4[l][i4];
        float wo0 = s_wout[2*i4],     wo1 = s_wout[2*i4 + 1];
        float wo2 = s_wout[2*i4 + 8], wo3 = s_wout[2*i4 + 9];
#pragma unroll
        for (int m = 0; m < MREP; m++){
            float da0[4], da1[4];
            float db0[4] = {0.f,0.f,0.f,0.f}, db1[4] = {0.f,0.f,0.f,0.f};
            mma16816_c(da0, Ahi[m], wf0.x, wf0.y, b4.x, b4.y);
            mma16816  (db0, Ahi[m], wf0.z, wf0.w);
            mma16816  (db0, Alo[m], wf0.x, wf0.y);
            mma16816_c(da1, Ahi[m], wf1.x, wf1.y, b4.z, b4.w);
            mma16816  (db1, Ahi[m], wf1.z, wf1.w);
            mma16816  (db1, Alo[m], wf1.x, wf1.y);

            float p0 = fmaxf(da0[0] + db0[0], 0.f) * wo0
                     + fmaxf(da0[1] + db0[1], 0.f) * wo1
                     + fmaxf(da1[0] + db1[0], 0.f) * wo2
                     + fmaxf(da1[1] + db1[1], 0.f) * wo3;
            float p1 = fmaxf(da0[2] + db0[2], 0.f) * wo0
                     + fmaxf(da0[3] + db0[3], 0.f) * wo1
                     + fmaxf(da1[2] + db1[2], 0.f) * wo2
                     + fmaxf(da1[3] + db1[3], 0.f) * wo3;
            p0 += __shfl_xor_sync(0xFFFFFFFFu, p0, 1);
            p0 += __shfl_xor_sync(0xFFFFFFFFu, p0, 2);
            p1 += __shfl_xor_sync(0xFFFFFFFFu, p1, 1);
            p1 += __shfl_xor_sync(0xFFFFFFFFu, p1, 2);
            if (i4 == 0){
                int s0 = base + m*16 + g;
                if (s0     < B) out[s0]     = p0 + s_bout;
                if (s0 + 8 < B) out[s0 + 8] = p1 + s_bout;
            }
        }
    }
}

extern "C" void kernel_launch(void* const* d_in, const int* in_sizes, int n_in,
                              void* d_out, int out_size)
{
    const float* x     = (const float*)d_in[0];
    const float* W_in  = (const float*)d_in[1];
    const float* b_in  = (const float*)d_in[2];
    const float* W_h   = (const float*)d_in[3];
    const float* b_h   = (const float*)d_in[4];
    const float* W_out = (const float*)d_in[5];
    const float* b_out = (const float*)d_in[6];
    float* out = (float*)d_out;

    int B = out_size;                    // 2^21, divisible by 256
    int grid = (B + SPC - 1) / SPC;      // 8192
    mlp_hmma_kernel<<<grid, TPB>>>(x, W_in, b_in, W_h, b_h, W_out, b_out, out, B);
}

// round 10
// speedup vs baseline: 1.9375x; 1.1185x over previous
#include <cuda_runtime.h>
#include <cuda_bf16.h>
#include <cstdint>

#define TPB      128
#define MREP     4              // m16 tiles per warp
#define SPW      (MREP * 16)    // 64 samples per warp
#define NWARP    (TPB / 32)
#define SPC      (SPW * NWARP)  // 256 samples per CTA
#define NLAYERS  31             // input layer + 30 hidden
#define H        16
#define S_IN     13

// pack two f32 into bf16x2 (low half = a, high half = b), round-to-nearest
__device__ __forceinline__ uint32_t cvt_bf16x2(float a, float b){
    uint32_t r;
    asm("cvt.rn.satfinite.bf16x2.f32 %0, %1, %2;" : "=r"(r) : "f"(b), "f"(a));
    return r;
}
// RN split (a,b) -> hi + lo bf16x2 (used for x and weights; preserves sign)
__device__ __forceinline__ void split_pair(float a, float b, uint32_t& hi, uint32_t& lo){
    hi = cvt_bf16x2(a, b);
    float fa = __uint_as_float(hi << 16);
    float fb = __uint_as_float(hi & 0xFFFF0000u);
    lo = cvt_bf16x2(a - fa, b - fb);
}

// fused ReLU + truncation split: hi = relu(trunc_bf16(d)), lo = relu-cvt(d - hi)
// trunc => lo in [0, ulp) for d>=0; for d<0 both hi and lo become 0.
__device__ __forceinline__ void relu_split(float d0, float d1, uint32_t& hi, uint32_t& lo){
    uint32_t h;
    asm("prmt.b32 %0, %1, %2, 0x7632;" : "=r"(h)
        : "r"(__float_as_uint(d0)), "r"(__float_as_uint(d1)));
    asm("max.bf16x2 %0, %1, %2;" : "=r"(h) : "r"(h), "r"(0u));
    float fa = __uint_as_float(h << 16);
    float fb = __uint_as_float(h & 0xFFFF0000u);
    uint32_t lo_;
    asm("cvt.rn.relu.satfinite.bf16x2.f32 %0, %1, %2;" : "=r"(lo_)
        : "f"(d1 - fb), "f"(d0 - fa));
    hi = h; lo = lo_;
}

// D += A(16x16 bf16, row) * B(16x8 bf16, col)
__device__ __forceinline__ void mma16816(float d[4], const uint32_t a[4],
                                         uint32_t b0, uint32_t b1){
    asm volatile(
        "mma.sync.aligned.m16n8k16.row.col.f32.bf16.bf16.f32 "
        "{%0,%1,%2,%3}, {%4,%5,%6,%7}, {%8,%9}, {%0,%1,%2,%3};"
        : "+f"(d[0]), "+f"(d[1]), "+f"(d[2]), "+f"(d[3])
        : "r"(a[0]), "r"(a[1]), "r"(a[2]), "r"(a[3]), "r"(b0), "r"(b1));
}
// D = A*B + C  (C = bias fragment; starts the accumulator chain)
__device__ __forceinline__ void mma16816_c(float d[4], const uint32_t a[4],
                                           uint32_t b0, uint32_t b1,
                                           float c0, float c1){
    asm volatile(
        "mma.sync.aligned.m16n8k16.row.col.f32.bf16.bf16.f32 "
        "{%0,%1,%2,%3}, {%4,%5,%6,%7}, {%8,%9}, {%10,%11,%10,%11};"
        : "=f"(d[0]), "=f"(d[1]), "=f"(d[2]), "=f"(d[3])
        : "r"(a[0]), "r"(a[1]), "r"(a[2]), "r"(a[3]), "r"(b0), "r"(b1),
          "f"(c0), "f"(c1));
}

__global__ __launch_bounds__(TPB, 5)
void mlp_hmma_kernel(const float* __restrict__ x,
                     const float* __restrict__ W_in,  const float* __restrict__ b_in,
                     const float* __restrict__ W_h,   const float* __restrict__ b_h,
                     const float* __restrict__ W_out, const float* __restrict__ b_out,
                     float* __restrict__ out, int B)
{
    // B-fragments per lane: {whi_r0, whi_r1, wlo_r0, wlo_r1} -> one LDS.128/tile/layer
    __shared__ uint4  s_wf[NLAYERS][2][32];
    __shared__ float4 s_b4[NLAYERS][4];
    __shared__ float  s_wout[16];
    __shared__ float  s_bout;

    const int t = threadIdx.x;

    // ---- weight prep: fragment order, bf16 hi/lo (RN split) ----
    for (int e = t; e < NLAYERS * 2 * 32; e += TPB){
        int l = e >> 6, r = e & 63, tile = r >> 5, tt = r & 31;
        int n = (tt >> 2) + tile * 8, i = tt & 3;
        float w[4];
#pragma unroll
        for (int j = 0; j < 4; j++){
            int k = 2*i + (j & 1) + (j >> 1) * 8;
            if (l == 0) w[j] = (k < S_IN) ? W_in[n * S_IN + k] : 0.f;
            else        w[j] = W_h[(l - 1) * (H * H) + n * H + k];
        }
        uint32_t h0, l0, h1, l1;
        split_pair(w[0], w[1], h0, l0);
        split_pair(w[2], w[3], h1, l1);
        s_wf[l][tile][tt] = make_uint4(h0, h1, l0, l1);
    }
    for (int e = t; e < NLAYERS * 4; e += TPB){
        int l = e >> 2, i = e & 3;
        const float* bb = (l == 0) ? b_in : (b_h + (l - 1) * H);
        s_b4[l][i] = make_float4(bb[2*i], bb[2*i+1], bb[2*i+8], bb[2*i+9]);
    }
    if (t < 16) s_wout[t] = W_out[t];
    if (t == 0) s_bout = b_out[0];
    __syncthreads();

    const int wid  = t >> 5;
    const int lane = t & 31;
    const int g    = lane >> 2;     // row group (0..7)
    const int i4   = lane & 3;      // col group (0..3)
    const int base = blockIdx.x * SPC + wid * SPW;

    // ---- A fragments for round 0: x rows {g, g+8}, cols {2i,2i+1,2i+8,2i+9} ----
    uint32_t Ahi[MREP][4], Alo[MREP][4];
#pragma unroll
    for (int m = 0; m < MREP; m++){
        const float* x0 = x + (size_t)(base + m*16 + g)     * S_IN;
        const float* x1 = x + (size_t)(base + m*16 + g + 8) * S_IN;
        float v0[4], v1[4];
#pragma unroll
        for (int j = 0; j < 4; j++){
            int k = 2*i4 + (j & 1) + (j >> 1) * 8;
            v0[j] = (k < S_IN) ? x0[k] : 0.f;
            v1[j] = (k < S_IN) ? x1[k] : 0.f;
        }
        split_pair(v0[0], v0[1], Ahi[m][0], Alo[m][0]);
        split_pair(v1[0], v1[1], Ahi[m][1], Alo[m][1]);
        split_pair(v0[2], v0[3], Ahi[m][2], Alo[m][2]);
        split_pair(v1[2], v1[3], Ahi[m][3], Alo[m][3]);
    }

    // ---- 30 chained layers: d = Ahi*Whi + bias; d += Ahi*Wlo; d += Alo*Whi ----
#pragma unroll 1
    for (int l = 0; l < NLAYERS - 1; l++){
        uint4  wf0 = s_wf[l][0][lane];
        uint4  wf1 = s_wf[l][1][lane];
        float4 b4  = s_b4[l][i4];
#pragma unroll
        for (int m = 0; m < MREP; m++){
            float d0[4], d1[4];
            mma16816_c(d0, Ahi[m], wf0.x, wf0.y, b4.x, b4.y);
            mma16816  (d0, Ahi[m], wf0.z, wf0.w);
            mma16816  (d0, Alo[m], wf0.x, wf0.y);
            mma16816_c(d1, Ahi[m], wf1.x, wf1.y, b4.z, b4.w);
            mma16816  (d1, Ahi[m], wf1.z, wf1.w);
            mma16816  (d1, Alo[m], wf1.x, wf1.y);

            relu_split(d0[0], d0[1], Ahi[m][0], Alo[m][0]);
            relu_split(d0[2], d0[3], Ahi[m][1], Alo[m][1]);
            relu_split(d1[0], d1[1], Ahi[m][2], Alo[m][2]);
            relu_split(d1[2], d1[3], Ahi[m][3], Alo[m][3]);
        }
    }

    // ---- final hidden layer + output dot, fused ----
    {
        const int l = NLAYERS - 1;
        uint4  wf0 = s_wf[l][0][lane];
        uint4  wf1 = s_wf[l][1][lane];
        float4 b4  = s_b4[l][i4];
        float wo0 = s_wout[2*i4],     wo1 = s_wout[2*i4 + 1];
        float wo2 = s_wout[2*i4 + 8], wo3 = s_wout[2*i4 + 9];
#pragma unroll
        for (int m = 0; m < MREP; m++){
            float d0[4], d1[4];
            mma16816_c(d0, Ahi[m], wf0.x, wf0.y, b4.x, b4.y);
            mma16816  (d0, Ahi[m], wf0.z, wf0.w);
            mma16816  (d0, Alo[m], wf0.x, wf0.y);
            mma16816_c(d1, Ahi[m], wf1.x, wf1.y, b4.z, b4.w);
            mma16816  (d1, Ahi[m], wf1.z, wf1.w);
            mma16816  (d1, Alo[m], wf1.x, wf1.y);

            float p0 = fmaxf(d0[0], 0.f) * wo0 + fmaxf(d0[1], 0.f) * wo1
                     + fmaxf(d1[0], 0.f) * wo2 + fmaxf(d1[1], 0.f) * wo3;
            float p1 = fmaxf(d0[2], 0.f) * wo0 + fmaxf(d0[3], 0.f) * wo1
                     + fmaxf(d1[2], 0.f) * wo2 + fmaxf(d1[3], 0.f) * wo3;
            p0 += __shfl_xor_sync(0xFFFFFFFFu, p0, 1);
            p0 += __shfl_xor_sync(0xFFFFFFFFu, p0, 2);
            p1 += __shfl_xor_sync(0xFFFFFFFFu, p1, 1);
            p1 += __shfl_xor_sync(0xFFFFFFFFu, p1, 2);
            if (i4 == 0){
                int s0 = base + m*16 + g;
                if (s0     < B) out[s0]     = p0 + s_bout;
                if (s0 + 8 < B) out[s0 + 8] = p1 + s_bout;
            }
        }
    }
}

extern "C" void kernel_launch(void* const* d_in, const int* in_sizes, int n_in,
                              void* d_out, int out_size)
{
    const float* x     = (const float*)d_in[0];
    const float* W_in  = (const float*)d_in[1];
    const float* b_in  = (const float*)d_in[2];
    const float* W_h   = (const float*)d_in[3];
    const float* b_h   = (const float*)d_in[4];
    const float* W_out = (const float*)d_in[5];
    const float* b_out = (const float*)d_in[6];
    float* out = (float*)d_out;

    int B = out_size;                    // 2^21, divisible by 256
    int grid = (B + SPC - 1) / SPC;      // 8192
    mlp_hmma_kernel<<<grid, TPB>>>(x, W_in, b_in, W_h, b_h, W_out, b_out, out, B);
}